// round 14
// baseline (speedup 1.0000x reference)
#include <cuda_runtime.h>
#include <cuda_bf16.h>
#include <math.h>
#include <stdint.h>

// Problem constants
#define BB 2
#define TT 2048
#define HH 16
#define DD 64
#define CC 1024
#define MM (BB*TT)   // 4096

// Scratch (allocation-free rule: __device__ globals)
__device__ float g_q[MM*CC];
__device__ float g_k[MM*CC];
__device__ float g_v[MM*CC];
__device__ float g_att[MM*CC];      // tf32-rounded at attention epilogue
__device__ float g_xt[MM*CC];       // tf32-rounded x
__device__ float g_wt[4*CC*CC];     // tf32-rounded Wq,Wk,Wv,Wp
// bf16 hi/lo packed planes for attention operands
__device__ uint32_t g_qhi[MM*HH*32];
__device__ uint32_t g_qlo[MM*HH*32];
__device__ uint32_t g_khi[MM*HH*32];
__device__ uint32_t g_klo[MM*HH*32];
__device__ uint32_t g_vhi[MM*HH*32];
__device__ uint32_t g_vlo[MM*HH*32];

// ---------------------------------------------------------------------------
// helpers
// ---------------------------------------------------------------------------
__device__ __forceinline__ float to_tf32(float x) {
    float r;
    asm("cvt.rna.tf32.f32 %0, %1;" : "=f"(r) : "f"(x));
    return r;
}

__device__ __forceinline__ void mma_tf32(float c[4], const uint32_t a[4],
                                         const uint32_t b[2])
{
    asm volatile(
        "mma.sync.aligned.m16n8k8.row.col.f32.tf32.tf32.f32 "
        "{%0,%1,%2,%3}, {%4,%5,%6,%7}, {%8,%9}, {%0,%1,%2,%3};"
        : "+f"(c[0]), "+f"(c[1]), "+f"(c[2]), "+f"(c[3])
        : "r"(a[0]), "r"(a[1]), "r"(a[2]), "r"(a[3]),
          "r"(b[0]), "r"(b[1]));
}

__device__ __forceinline__ void mma_bf16(float c[4], const uint32_t a[4],
                                         const uint32_t b[2])
{
    asm volatile(
        "mma.sync.aligned.m16n8k16.row.col.f32.bf16.bf16.f32 "
        "{%0,%1,%2,%3}, {%4,%5,%6,%7}, {%8,%9}, {%0,%1,%2,%3};"
        : "+f"(c[0]), "+f"(c[1]), "+f"(c[2]), "+f"(c[3])
        : "r"(a[0]), "r"(a[1]), "r"(a[2]), "r"(a[3]),
          "r"(b[0]), "r"(b[1]));
}

__device__ __forceinline__ uint32_t smem_u32(const void* p) {
    uint32_t a;
    asm("{ .reg .u64 t; cvta.to.shared.u64 t, %1; cvt.u32.u64 %0, t; }"
        : "=r"(a) : "l"(p));
    return a;
}

__device__ __forceinline__ uint32_t pack2(float e0, float e1) {
    __nv_bfloat162 t = __floats2bfloat162_rn(e0, e1);
    return *(uint32_t*)&t;
}
__device__ __forceinline__ float bf16f(float v) {
    return __bfloat162float(__float2bfloat16_rn(v));
}

// ---------------------------------------------------------------------------
// Prep: round x and the 4 weight matrices to tf32 bit patterns.
// ---------------------------------------------------------------------------
#define X4 (MM*CC/4)
#define W4 (CC*CC/4)
#define PREP_TOTAL4 (X4 + 4*W4)

__global__ __launch_bounds__(256)
void prep_round_kernel(const float* __restrict__ x,
                       const float* __restrict__ Wq, const float* __restrict__ Wk,
                       const float* __restrict__ Wv, const float* __restrict__ Wp)
{
    int i = blockIdx.x * blockDim.x + threadIdx.x;
    if (i >= PREP_TOTAL4) return;
    const float* src; float* dst; int off;
    if (i < X4) {
        src = x; dst = g_xt; off = i;
    } else {
        int j = i - X4;
        int w = j >> 18;
        off = j & (W4 - 1);
        src = (w == 0) ? Wq : (w == 1) ? Wk : (w == 2) ? Wv : Wp;
        dst = g_wt + (size_t)w * (CC*CC);
    }
    float4 v = ((const float4*)src)[off];
    v.x = to_tf32(v.x); v.y = to_tf32(v.y);
    v.z = to_tf32(v.z); v.w = to_tf32(v.w);
    ((float4*)dst)[off] = v;
}

// ===========================================================================
// tf32 mma.sync GEMM: BK=32, 3-stage cp.async pipeline (32 iterations).
// out[m,n] = sum_k A[m,k]*W[n,k] + bias[n]; operands pre-rounded to tf32.
// Smem m-major [128][36] per tile (stride 36: conflict-free fragment LDS).
// ===========================================================================
#define GK 1024
#define GN 1024
#define BKt 32
#define STAGES 3
#define AS_STRIDE 36
#define TILE_FLOATS (128*AS_STRIDE)          // 4608
#define STAGE_BYTES (2*TILE_FLOATS*4)        // 36864
#define MM_SMEM_BYTES (STAGES*STAGE_BYTES)   // 110592

__device__ __forceinline__ void mm128_body(
    const float* __restrict__ A, const float* __restrict__ W,
    const float* __restrict__ bias, float* __restrict__ out)
{
    extern __shared__ float sm[];
    uint32_t smb = smem_u32(sm);

    const int tid = threadIdx.x;
    const int wid = tid >> 5;
    const int lane = tid & 31;
    const int grp = lane >> 2;
    const int tig = lane & 3;
    const int wm = wid >> 1;
    const int wn = wid & 1;

    const int m0 = blockIdx.y * 128;
    const int n0 = blockIdx.x * 128;

    // loader: row = tid>>1 (0..127), half = (tid&1)*16 floats; 4 chunks of 16B
    const int lr = tid >> 1;
    const int lh = (tid & 1) * 16;

    const float* Ag = A + (size_t)(m0 + lr) * GK + lh;
    const float* Wg = W + (size_t)(n0 + lr) * GK + lh;
    const uint32_t sA = smb + (lr * AS_STRIDE + lh) * 4;
    const uint32_t sB = sA + TILE_FLOATS * 4;

#define ISSUE_MM(it_, st_)                                                  \
    do {                                                                    \
        const float* ag_ = Ag + (it_) * BKt;                                \
        const float* wg_ = Wg + (it_) * BKt;                                \
        uint32_t a_ = sA + (st_) * STAGE_BYTES;                             \
        uint32_t b_ = sB + (st_) * STAGE_BYTES;                             \
        _Pragma("unroll")                                                   \
        for (int j_ = 0; j_ < 4; j_++) {                                    \
            asm volatile("cp.async.cg.shared.global [%0], [%1], 16;"        \
                         :: "r"(a_ + j_*16), "l"(ag_ + j_*4) : "memory");   \
            asm volatile("cp.async.cg.shared.global [%0], [%1], 16;"        \
                         :: "r"(b_ + j_*16), "l"(wg_ + j_*4) : "memory");   \
        }                                                                   \
    } while (0)

    float c[2][8][4];
#pragma unroll
    for (int mt = 0; mt < 2; mt++)
#pragma unroll
        for (int nt = 0; nt < 8; nt++)
#pragma unroll
            for (int i = 0; i < 4; i++) c[mt][nt][i] = 0.f;

    // prologue: issue tiles 0..STAGES-2
#pragma unroll
    for (int s = 0; s < STAGES - 1; s++) {
        ISSUE_MM(s, s);
        asm volatile("cp.async.commit_group;" ::: "memory");
    }

    const int NT = GK / BKt;    // 32
    for (int it = 0; it < NT; it++) {
        asm volatile("cp.async.wait_group %0;" :: "n"(STAGES - 2) : "memory");
        __syncthreads();

        if (it + STAGES - 1 < NT)
            ISSUE_MM(it + STAGES - 1, (it + STAGES - 1) % STAGES);
        asm volatile("cp.async.commit_group;" ::: "memory");

        const float* AsS = sm + (it % STAGES) * (2 * TILE_FLOATS);
        const float* BsS = AsS + TILE_FLOATS;
#pragma unroll
        for (int ks = 0; ks < 4; ks++) {
            int kk = ks * 8;
            uint32_t afr[2][4];
#pragma unroll
            for (int mt = 0; mt < 2; mt++) {
                int rm = wm * 32 + mt * 16;
                afr[mt][0] = __float_as_uint(AsS[(rm+grp)  *AS_STRIDE + kk+tig]);
                afr[mt][1] = __float_as_uint(AsS[(rm+grp+8)*AS_STRIDE + kk+tig]);
                afr[mt][2] = __float_as_uint(AsS[(rm+grp)  *AS_STRIDE + kk+tig+4]);
                afr[mt][3] = __float_as_uint(AsS[(rm+grp+8)*AS_STRIDE + kk+tig+4]);
            }
            uint32_t bfr[8][2];
#pragma unroll
            for (int nt = 0; nt < 8; nt++) {
                int cn = wn * 64 + nt * 8;
                bfr[nt][0] = __float_as_uint(BsS[(cn+grp)*AS_STRIDE + kk+tig]);
                bfr[nt][1] = __float_as_uint(BsS[(cn+grp)*AS_STRIDE + kk+tig+4]);
            }
#pragma unroll
            for (int mt = 0; mt < 2; mt++)
#pragma unroll
                for (int nt = 0; nt < 8; nt++)
                    mma_tf32(c[mt][nt], afr[mt], bfr[nt]);
        }
    }
#undef ISSUE_MM

#pragma unroll
    for (int mt = 0; mt < 2; mt++) {
        int row = m0 + wm*32 + mt*16 + grp;
#pragma unroll
        for (int nt = 0; nt < 8; nt++) {
            int col = n0 + wn*64 + nt*8 + tig*2;
            float2 bv = *(const float2*)(bias + col);
            float2 o0, o1;
            o0.x = c[mt][nt][0] + bv.x;
            o0.y = c[mt][nt][1] + bv.y;
            o1.x = c[mt][nt][2] + bv.x;
            o1.y = c[mt][nt][3] + bv.y;
            *(float2*)(out + (size_t)row * GN + col) = o0;
            *(float2*)(out + (size_t)(row + 8) * GN + col) = o1;
        }
    }
}

__global__ __launch_bounds__(256, 2)
void mm_qkv_kernel(const float* __restrict__ bq,
                   const float* __restrict__ bk,
                   const float* __restrict__ bv)
{
    const float* b; float* out;
    const float* W = g_wt + (size_t)blockIdx.z * (CC*CC);
    if (blockIdx.z == 0)      { b = bq; out = g_q; }
    else if (blockIdx.z == 1) { b = bk; out = g_k; }
    else                      { b = bv; out = g_v; }
    mm128_body(g_xt, W, b, out);
}

__global__ __launch_bounds__(256, 2)
void mm_proj_kernel(const float* __restrict__ bp, float* __restrict__ out)
{
    mm128_body(g_att, g_wt + (size_t)3 * (CC*CC), bp, out);
}

// ---------------------------------------------------------------------------
// RoPE + bf16 hi/lo pair packing (unchanged from R13).
// ---------------------------------------------------------------------------
#define QK_ITEMS (BB*TT*HH*32)
#define V_ITEMS  (BB*(TT/2)*HH*64)
#define ROPE_TOTAL (2*QK_ITEMS + V_ITEMS)

__device__ __forceinline__ float rope_dim(const float* p, int d, int t) {
    const float L = 13.287712379549449f / 32.0f;  // log2(10000)/32
    int j = d & 31;
    float inv = exp2f(-(float)j * L);
    float ang = (float)t * inv;
    float c, s;
    sincosf(ang, &s, &c);
    return (d < 32) ? (p[d] * c - p[d + 32] * s)
                    : (p[d] * c + p[d - 32] * s);
}

__global__ __launch_bounds__(256)
void rope_pack_kernel()
{
    int idx = blockIdx.x * blockDim.x + threadIdx.x;
    if (idx >= ROPE_TOTAL) return;

    if (idx < 2 * QK_ITEMS) {
        int seg = idx / QK_ITEMS;        // 0: q, 1: k
        int i = idx - seg * QK_ITEMS;
        int dp = i & 31;
        int h = (i >> 5) & 15;
        int t = (i >> 9) & 2047;
        int b = i >> 20;
        size_t base = (((size_t)(b*TT + t))*HH + h) * DD;
        const float* p = (seg == 0 ? g_q : g_k) + base;
        int d0 = 2 * dp;
        float o0 = rope_dim(p, d0, t);
        float o1 = rope_dim(p, d0 + 1, t);
        float h0 = bf16f(o0), h1 = bf16f(o1);
        size_t oi = (((size_t)(b*TT + t))*HH + h) * 32 + dp;
        if (seg == 0) {
            g_qhi[oi] = pack2(h0, h1);
            g_qlo[oi] = pack2(o0 - h0, o1 - h1);
        } else {
            g_khi[oi] = pack2(h0, h1);
            g_klo[oi] = pack2(o0 - h0, o1 - h1);
        }
    } else {
        int i = idx - 2 * QK_ITEMS;
        int d = i & 63;
        int h = (i >> 6) & 15;
        int t2 = (i >> 10) & 1023;
        int b = i >> 20;
        float v0 = g_v[(((size_t)(b*TT + 2*t2    ))*HH + h) * DD + d];
        float v1 = g_v[(((size_t)(b*TT + 2*t2 + 1))*HH + h) * DD + d];
        float h0 = bf16f(v0), h1 = bf16f(v1);
        size_t oi = (((size_t)(b*(TT/2) + t2))*HH + h) * 64 + d;
        g_vhi[oi] = pack2(h0, h1);
        g_vlo[oi] = pack2(v0 - h0, v1 - h1);
    }
}

// ===========================================================================
// Tensor-core causal flash attention, bf16 hi/lo compensated (unchanged
// from R13 — confirmed 238us).
// ===========================================================================
#define KST 36
#define VST 72
#define ATT_STAGE_W 4608
#define ATT_SMEM_BYTES (2 * ATT_STAGE_W * 4)   // 36864

__global__ __launch_bounds__(256, 2)
void attn_kernel()
{
    extern __shared__ uint32_t smw[];
    const uint32_t smb = smem_u32(smw);

    const int tid = threadIdx.x;
    const int lane = tid & 31, wid = tid >> 5;
    const int grp = lane >> 2, tig = lane & 3;
    const int qtile = gridDim.x - 1 - blockIdx.x;
    const int bh = blockIdx.y;
    const int b = bh >> 4, h = bh & 15;
    const int q0 = qtile * 128;
    const int wr0 = wid * 16;

#define ISSUE_TILE(kt_, buf_)                                               \
    do {                                                                    \
        int k0_ = (kt_) * 32;                                               \
        uint32_t st_ = smb + (buf_) * (ATT_STAGE_W * 4);                    \
        {   /* Khi */                                                       \
            int r_ = tid >> 3, ch_ = tid & 7;                               \
            const uint32_t* s_ = g_khi + (((size_t)(b*TT + k0_ + r_))*HH + h)*32 + ch_*4; \
            asm volatile("cp.async.cg.shared.global [%0], [%1], 16;"        \
                :: "r"(st_ + r_*144 + ch_*16), "l"(s_) : "memory");         \
        }                                                                   \
        {   /* Klo */                                                       \
            int r_ = tid >> 3, ch_ = tid & 7;                               \
            const uint32_t* s_ = g_klo + (((size_t)(b*TT + k0_ + r_))*HH + h)*32 + ch_*4; \
            asm volatile("cp.async.cg.shared.global [%0], [%1], 16;"        \
                :: "r"(st_ + 4608 + r_*144 + ch_*16), "l"(s_) : "memory");  \
        }                                                                   \
        {   /* Vhi */                                                       \
            int r_ = tid >> 4, ch_ = tid & 15;                              \
            const uint32_t* s_ = g_vhi + (((size_t)(b*(TT/2) + k0_/2 + r_))*HH + h)*64 + ch_*4; \
            asm volatile("cp.async.cg.shared.global [%0], [%1], 16;"        \
                :: "r"(st_ + 9216 + r_*288 + ch_*16), "l"(s_) : "memory");  \
        }                                                                   \
        {   /* Vlo */                                                       \
            int r_ = tid >> 4, ch_ = tid & 15;                              \
            const uint32_t* s_ = g_vlo + (((size_t)(b*(TT/2) + k0_/2 + r_))*HH + h)*64 + ch_*4; \
            asm volatile("cp.async.cg.shared.global [%0], [%1], 16;"        \
                :: "r"(st_ + 13824 + r_*288 + ch_*16), "l"(s_) : "memory"); \
        }                                                                   \
    } while (0)

    ISSUE_TILE(0, 0);
    asm volatile("cp.async.commit_group;" ::: "memory");

    uint32_t qhi2[4][4], qlo2[4][4];
    {
        size_t r0i = (((size_t)(b*TT + q0 + wr0 + grp))*HH + h) * 32;
        size_t r8i = r0i + (size_t)8 * HH * 32;
#pragma unroll
        for (int ksb = 0; ksb < 4; ksb++) {
            int dp = 8*ksb + tig;
            qhi2[ksb][0] = g_qhi[r0i + dp];
            qhi2[ksb][1] = g_qhi[r8i + dp];
            qhi2[ksb][2] = g_qhi[r0i + dp + 4];
            qhi2[ksb][3] = g_qhi[r8i + dp + 4];
            qlo2[ksb][0] = g_qlo[r0i + dp];
            qlo2[ksb][1] = g_qlo[r8i + dp];
            qlo2[ksb][2] = g_qlo[r0i + dp + 4];
            qlo2[ksb][3] = g_qlo[r8i + dp + 4];
        }
    }

    float o[8][4];
#pragma unroll
    for (int nt = 0; nt < 8; nt++)
#pragma unroll
        for (int e = 0; e < 4; e++) o[nt][e] = 0.f;
    float mr0 = -1e30f, mr1 = -1e30f, lr0v = 0.f, lr1v = 0.f;

    const int row0 = q0 + wr0 + grp;
    const int row1 = row0 + 8;
    const int ntiles = 4*qtile + 4;

    for (int kt = 0; kt < ntiles; kt++) {
        int buf = kt & 1;
        int k0 = kt * 32;

        if (kt + 1 < ntiles) ISSUE_TILE(kt + 1, buf ^ 1);
        asm volatile("cp.async.commit_group;" ::: "memory");
        asm volatile("cp.async.wait_group 1;" ::: "memory");
        __syncthreads();

        if (k0 <= q0 + wr0 + 15) {
            const uint32_t* Khi_s = smw + buf * ATT_STAGE_W;
            const uint32_t* Klo_s = Khi_s + 1152;
            const uint32_t* Vhi_s = Khi_s + 2304;
            const uint32_t* Vlo_s = Khi_s + 3456;

            float c[4][4];
#pragma unroll
            for (int nt = 0; nt < 4; nt++)
#pragma unroll
                for (int e = 0; e < 4; e++) c[nt][e] = 0.f;

#pragma unroll
            for (int ksb = 0; ksb < 4; ksb++) {
#pragma unroll
                for (int nt = 0; nt < 4; nt++) {
                    int krow = (nt*8 + grp) * KST;
                    int dp = 8*ksb + tig;
                    uint32_t bhi[2] = {Khi_s[krow + dp], Khi_s[krow + dp + 4]};
                    uint32_t blo[2] = {Klo_s[krow + dp], Klo_s[krow + dp + 4]};
                    mma_bf16(c[nt], qhi2[ksb], bhi);
                    mma_bf16(c[nt], qhi2[ksb], blo);
                    mma_bf16(c[nt], qlo2[ksb], bhi);
                }
            }

#pragma unroll
            for (int nt = 0; nt < 4; nt++) {
                int col = k0 + nt*8 + tig*2;
                c[nt][0] = (col     <= row0) ? c[nt][0] * 0.125f : -1e30f;
                c[nt][1] = (col + 1 <= row0) ? c[nt][1] * 0.125f : -1e30f;
                c[nt][2] = (col     <= row1) ? c[nt][2] * 0.125f : -1e30f;
                c[nt][3] = (col + 1 <= row1) ? c[nt][3] * 0.125f : -1e30f;
            }

            float mx0 = -1e30f, mx1 = -1e30f;
#pragma unroll
            for (int nt = 0; nt < 4; nt++) {
                mx0 = fmaxf(mx0, fmaxf(c[nt][0], c[nt][1]));
                mx1 = fmaxf(mx1, fmaxf(c[nt][2], c[nt][3]));
            }
            mx0 = fmaxf(mx0, __shfl_xor_sync(0xffffffffu, mx0, 1));
            mx0 = fmaxf(mx0, __shfl_xor_sync(0xffffffffu, mx0, 2));
            mx1 = fmaxf(mx1, __shfl_xor_sync(0xffffffffu, mx1, 1));
            mx1 = fmaxf(mx1, __shfl_xor_sync(0xffffffffu, mx1, 2));

            float nm0 = fmaxf(mr0, mx0), nm1 = fmaxf(mr1, mx1);
            float corr0 = __expf(mr0 - nm0), corr1 = __expf(mr1 - nm1);
            mr0 = nm0; mr1 = nm1;

            float rs0 = 0.f, rs1 = 0.f;
#pragma unroll
            for (int nt = 0; nt < 4; nt++) {
                c[nt][0] = __expf(c[nt][0] - nm0);
                c[nt][1] = __expf(c[nt][1] - nm0);
                c[nt][2] = __expf(c[nt][2] - nm1);
                c[nt][3] = __expf(c[nt][3] - nm1);
                rs0 += c[nt][0] + c[nt][1];
                rs1 += c[nt][2] + c[nt][3];
            }
            rs0 += __shfl_xor_sync(0xffffffffu, rs0, 1);
            rs0 += __shfl_xor_sync(0xffffffffu, rs0, 2);
            rs1 += __shfl_xor_sync(0xffffffffu, rs1, 1);
            rs1 += __shfl_xor_sync(0xffffffffu, rs1, 2);
            lr0v = lr0v * corr0 + rs0;
            lr1v = lr1v * corr1 + rs1;

#pragma unroll
            for (int nt = 0; nt < 8; nt++) {
                o[nt][0] *= corr0; o[nt][1] *= corr0;
                o[nt][2] *= corr1; o[nt][3] *= corr1;
            }

#pragma unroll
            for (int ksbv = 0; ksbv < 2; ksbv++) {
                float p00 = c[2*ksbv][0],   p01 = c[2*ksbv][1];
                float p02 = c[2*ksbv][2],   p03 = c[2*ksbv][3];
                float p10 = c[2*ksbv+1][0], p11 = c[2*ksbv+1][1];
                float p12 = c[2*ksbv+1][2], p13 = c[2*ksbv+1][3];
                float h00 = bf16f(p00), h01 = bf16f(p01);
                float h02 = bf16f(p02), h03 = bf16f(p03);
                float h10 = bf16f(p10), h11 = bf16f(p11);
                float h12 = bf16f(p12), h13 = bf16f(p13);
                uint32_t pah[4] = { pack2(h00, h01), pack2(h02, h03),
                                    pack2(h10, h11), pack2(h12, h13) };
                uint32_t pal[4] = { pack2(p00-h00, p01-h01), pack2(p02-h02, p03-h03),
                                    pack2(p10-h10, p11-h11), pack2(p12-h12, p13-h13) };
#pragma unroll
                for (int nt = 0; nt < 8; nt++) {
                    int vrow0 = (8*ksbv + tig) * VST + nt*8 + grp;
                    int vrow1 = vrow0 + 4*VST;
                    uint32_t bhi[2] = {Vhi_s[vrow0], Vhi_s[vrow1]};
                    uint32_t blo[2] = {Vlo_s[vrow0], Vlo_s[vrow1]};
                    mma_bf16(o[nt], pah, bhi);
                    mma_bf16(o[nt], pah, blo);
                    mma_bf16(o[nt], pal, bhi);
                }
            }
        }
        __syncthreads();
    }
#undef ISSUE_TILE

    float i0 = 1.f / lr0v, i1 = 1.f / lr1v;
    float* y0 = g_att + ((size_t)(b*TT + q0 + wr0 + grp))*CC + h*DD;
    float* y1 = g_att + ((size_t)(b*TT + q0 + wr0 + grp + 8))*CC + h*DD;
#pragma unroll
    for (int nt = 0; nt < 8; nt++) {
        *(float2*)(y0 + nt*8 + tig*2) =
            make_float2(to_tf32(o[nt][0]*i0), to_tf32(o[nt][1]*i0));
        *(float2*)(y1 + nt*8 + tig*2) =
            make_float2(to_tf32(o[nt][2]*i1), to_tf32(o[nt][3]*i1));
    }
}

// ---------------------------------------------------------------------------
extern "C" void kernel_launch(void* const* d_in, const int* in_sizes, int n_in,
                              void* d_out, int out_size)
{
    const float* x  = (const float*)d_in[0];
    const float* Wq = (const float*)d_in[1];
    const float* bq = (const float*)d_in[2];
    const float* Wk = (const float*)d_in[3];
    const float* bk = (const float*)d_in[4];
    const float* Wv = (const float*)d_in[5];
    const float* bv = (const float*)d_in[6];
    const float* Wp = (const float*)d_in[7];
    const float* bp = (const float*)d_in[8];
    float* out = (float*)d_out;

    cudaFuncSetAttribute(attn_kernel,
                         cudaFuncAttributeMaxDynamicSharedMemorySize,
                         ATT_SMEM_BYTES);
    cudaFuncSetAttribute(mm_qkv_kernel,
                         cudaFuncAttributeMaxDynamicSharedMemorySize,
                         MM_SMEM_BYTES);
    cudaFuncSetAttribute(mm_proj_kernel,
                         cudaFuncAttributeMaxDynamicSharedMemorySize,
                         MM_SMEM_BYTES);

    // 0. Pre-round x and weights to tf32 bit patterns
    prep_round_kernel<<<(PREP_TOTAL4 + 255) / 256, 256>>>(x, Wq, Wk, Wv, Wp);

    // 1. QKV projections (tf32 mma.sync, BK=32, 3-stage cp.async)
    dim3 qkv_grid(GN/128, MM/128, 3);
    mm_qkv_kernel<<<qkv_grid, 256, MM_SMEM_BYTES>>>(bq, bk, bv);

    // 2. RoPE + bf16 hi/lo packing of Q, K, V
    rope_pack_kernel<<<(ROPE_TOTAL + 255) / 256, 256>>>();

    // 3. bf16 compensated causal flash attention
    dim3 attn_grid(TT/128, BB*HH);
    attn_kernel<<<attn_grid, 256, ATT_SMEM_BYTES>>>();

    // 4. Output projection (tf32 mma.sync, BK=32, 3-stage cp.async)
    dim3 proj_grid(GN/128, MM/128);
    mm_proj_kernel<<<proj_grid, 256, MM_SMEM_BYTES>>>(bp, out);
}

// round 15
// speedup vs baseline: 1.0542x; 1.0542x over previous
#include <cuda_runtime.h>
#include <cuda_bf16.h>
#include <math.h>
#include <stdint.h>

// Problem constants
#define BB 2
#define TT 2048
#define HH 16
#define DD 64
#define CC 1024
#define MM (BB*TT)   // 4096

// Scratch (allocation-free rule: __device__ globals)
__device__ float g_q[MM*CC];
__device__ float g_k[MM*CC];
__device__ float g_v[MM*CC];
__device__ float g_att[MM*CC];      // tf32-rounded at attention epilogue
__device__ float g_xt[MM*CC];       // tf32-rounded x
__device__ float g_wt[4*CC*CC];     // tf32-rounded Wq,Wk,Wv,Wp
// bf16 hi/lo packed planes for attention operands
__device__ uint32_t g_qhi[MM*HH*32];
__device__ uint32_t g_qlo[MM*HH*32];
__device__ uint32_t g_khi[MM*HH*32];
__device__ uint32_t g_klo[MM*HH*32];
__device__ uint32_t g_vhi[MM*HH*32];
__device__ uint32_t g_vlo[MM*HH*32];

// ---------------------------------------------------------------------------
// helpers
// ---------------------------------------------------------------------------
__device__ __forceinline__ float to_tf32(float x) {
    float r;
    asm("cvt.rna.tf32.f32 %0, %1;" : "=f"(r) : "f"(x));
    return r;
}

__device__ __forceinline__ void mma_tf32(float c[4], const uint32_t a[4],
                                         const uint32_t b[2])
{
    asm volatile(
        "mma.sync.aligned.m16n8k8.row.col.f32.tf32.tf32.f32 "
        "{%0,%1,%2,%3}, {%4,%5,%6,%7}, {%8,%9}, {%0,%1,%2,%3};"
        : "+f"(c[0]), "+f"(c[1]), "+f"(c[2]), "+f"(c[3])
        : "r"(a[0]), "r"(a[1]), "r"(a[2]), "r"(a[3]),
          "r"(b[0]), "r"(b[1]));
}

__device__ __forceinline__ void mma_bf16(float c[4], const uint32_t a[4],
                                         const uint32_t b[2])
{
    asm volatile(
        "mma.sync.aligned.m16n8k16.row.col.f32.bf16.bf16.f32 "
        "{%0,%1,%2,%3}, {%4,%5,%6,%7}, {%8,%9}, {%0,%1,%2,%3};"
        : "+f"(c[0]), "+f"(c[1]), "+f"(c[2]), "+f"(c[3])
        : "r"(a[0]), "r"(a[1]), "r"(a[2]), "r"(a[3]),
          "r"(b[0]), "r"(b[1]));
}

__device__ __forceinline__ uint32_t smem_u32(const void* p) {
    uint32_t a;
    asm("{ .reg .u64 t; cvta.to.shared.u64 t, %1; cvt.u32.u64 %0, t; }"
        : "=r"(a) : "l"(p));
    return a;
}

__device__ __forceinline__ uint32_t pack2(float e0, float e1) {
    __nv_bfloat162 t = __floats2bfloat162_rn(e0, e1);
    return *(uint32_t*)&t;
}
__device__ __forceinline__ float bf16f(float v) {
    return __bfloat162float(__float2bfloat16_rn(v));
}

// ---------------------------------------------------------------------------
// Prep: round x and the 4 weight matrices to tf32 bit patterns.
// ---------------------------------------------------------------------------
#define X4 (MM*CC/4)
#define W4 (CC*CC/4)
#define PREP_TOTAL4 (X4 + 4*W4)

__global__ __launch_bounds__(256)
void prep_round_kernel(const float* __restrict__ x,
                       const float* __restrict__ Wq, const float* __restrict__ Wk,
                       const float* __restrict__ Wv, const float* __restrict__ Wp)
{
    int i = blockIdx.x * blockDim.x + threadIdx.x;
    if (i >= PREP_TOTAL4) return;
    const float* src; float* dst; int off;
    if (i < X4) {
        src = x; dst = g_xt; off = i;
    } else {
        int j = i - X4;
        int w = j >> 18;
        off = j & (W4 - 1);
        src = (w == 0) ? Wq : (w == 1) ? Wk : (w == 2) ? Wv : Wp;
        dst = g_wt + (size_t)w * (CC*CC);
    }
    float4 v = ((const float4*)src)[off];
    v.x = to_tf32(v.x); v.y = to_tf32(v.y);
    v.z = to_tf32(v.z); v.w = to_tf32(v.w);
    ((float4*)dst)[off] = v;
}

// ===========================================================================
// tf32 mma.sync GEMM with 4-stage cp.async pipeline (R13 config — confirmed).
// ===========================================================================
#define GK 1024
#define GN 1024
#define BKt 16
#define STAGES 4
#define AS_STRIDE 20
#define TILE_FLOATS (128*AS_STRIDE)
#define STAGE_BYTES (2*TILE_FLOATS*4)
#define MM_SMEM_BYTES (STAGES*STAGE_BYTES)   // 81920

__device__ __forceinline__ void mm128_body(
    const float* __restrict__ A, const float* __restrict__ W,
    const float* __restrict__ bias, float* __restrict__ out)
{
    extern __shared__ float sm[];
    uint32_t smb = smem_u32(sm);

    const int tid = threadIdx.x;
    const int wid = tid >> 5;
    const int lane = tid & 31;
    const int grp = lane >> 2;
    const int tig = lane & 3;
    const int wm = wid >> 1;
    const int wn = wid & 1;

    const int m0 = blockIdx.y * 128;
    const int n0 = blockIdx.x * 128;

    const int lr = tid >> 1;
    const int lkc = (tid & 1) * 2;

    const float* Ag = A + (size_t)(m0 + lr) * GK + lkc * 4;
    const float* Wg = W + (size_t)(n0 + lr) * GK + lkc * 4;
    const uint32_t sA = smb + (lr * AS_STRIDE + lkc * 4) * 4;
    const uint32_t sB = sA + TILE_FLOATS * 4;

#define ISSUE_MM(it_, st_)                                                  \
    do {                                                                    \
        const float* ag_ = Ag + (it_) * BKt;                                \
        const float* wg_ = Wg + (it_) * BKt;                                \
        uint32_t a_ = sA + (st_) * STAGE_BYTES;                             \
        uint32_t b_ = sB + (st_) * STAGE_BYTES;                             \
        asm volatile("cp.async.cg.shared.global [%0], [%1], 16;"            \
                     :: "r"(a_), "l"(ag_) : "memory");                      \
        asm volatile("cp.async.cg.shared.global [%0], [%1], 16;"            \
                     :: "r"(a_ + 16), "l"(ag_ + 4) : "memory");             \
        asm volatile("cp.async.cg.shared.global [%0], [%1], 16;"            \
                     :: "r"(b_), "l"(wg_) : "memory");                      \
        asm volatile("cp.async.cg.shared.global [%0], [%1], 16;"            \
                     :: "r"(b_ + 16), "l"(wg_ + 4) : "memory");             \
    } while (0)

    float c[2][8][4];
#pragma unroll
    for (int mt = 0; mt < 2; mt++)
#pragma unroll
        for (int nt = 0; nt < 8; nt++)
#pragma unroll
            for (int i = 0; i < 4; i++) c[mt][nt][i] = 0.f;

#pragma unroll
    for (int s = 0; s < STAGES - 1; s++) {
        ISSUE_MM(s, s);
        asm volatile("cp.async.commit_group;" ::: "memory");
    }

    const int NT = GK / BKt;
    for (int it = 0; it < NT; it++) {
        asm volatile("cp.async.wait_group %0;" :: "n"(STAGES - 2) : "memory");
        __syncthreads();

        if (it + STAGES - 1 < NT)
            ISSUE_MM(it + STAGES - 1, (it + STAGES - 1) % STAGES);
        asm volatile("cp.async.commit_group;" ::: "memory");

        const float* AsS = sm + (it % STAGES) * (2 * TILE_FLOATS);
        const float* BsS = AsS + TILE_FLOATS;
#pragma unroll
        for (int ks = 0; ks < 2; ks++) {
            int kk = ks * 8;
            uint32_t afr[2][4];
#pragma unroll
            for (int mt = 0; mt < 2; mt++) {
                int rm = wm * 32 + mt * 16;
                afr[mt][0] = __float_as_uint(AsS[(rm+grp)  *AS_STRIDE + kk+tig]);
                afr[mt][1] = __float_as_uint(AsS[(rm+grp+8)*AS_STRIDE + kk+tig]);
                afr[mt][2] = __float_as_uint(AsS[(rm+grp)  *AS_STRIDE + kk+tig+4]);
                afr[mt][3] = __float_as_uint(AsS[(rm+grp+8)*AS_STRIDE + kk+tig+4]);
            }
            uint32_t bfr[8][2];
#pragma unroll
            for (int nt = 0; nt < 8; nt++) {
                int cn = wn * 64 + nt * 8;
                bfr[nt][0] = __float_as_uint(BsS[(cn+grp)*AS_STRIDE + kk+tig]);
                bfr[nt][1] = __float_as_uint(BsS[(cn+grp)*AS_STRIDE + kk+tig+4]);
            }
#pragma unroll
            for (int mt = 0; mt < 2; mt++)
#pragma unroll
                for (int nt = 0; nt < 8; nt++)
                    mma_tf32(c[mt][nt], afr[mt], bfr[nt]);
        }
    }
#undef ISSUE_MM

#pragma unroll
    for (int mt = 0; mt < 2; mt++) {
        int row = m0 + wm*32 + mt*16 + grp;
#pragma unroll
        for (int nt = 0; nt < 8; nt++) {
            int col = n0 + wn*64 + nt*8 + tig*2;
            float2 bv = *(const float2*)(bias + col);
            float2 o0, o1;
            o0.x = c[mt][nt][0] + bv.x;
            o0.y = c[mt][nt][1] + bv.y;
            o1.x = c[mt][nt][2] + bv.x;
            o1.y = c[mt][nt][3] + bv.y;
            *(float2*)(out + (size_t)row * GN + col) = o0;
            *(float2*)(out + (size_t)(row + 8) * GN + col) = o1;
        }
    }
}

__global__ __launch_bounds__(256, 2)
void mm_qkv_kernel(const float* __restrict__ bq,
                   const float* __restrict__ bk,
                   const float* __restrict__ bv)
{
    const float* b; float* out;
    const float* W = g_wt + (size_t)blockIdx.z * (CC*CC);
    if (blockIdx.z == 0)      { b = bq; out = g_q; }
    else if (blockIdx.z == 1) { b = bk; out = g_k; }
    else                      { b = bv; out = g_v; }
    mm128_body(g_xt, W, b, out);
}

__global__ __launch_bounds__(256, 2)
void mm_proj_kernel(const float* __restrict__ bp, float* __restrict__ out)
{
    mm128_body(g_att, g_wt + (size_t)3 * (CC*CC), bp, out);
}

// ---------------------------------------------------------------------------
// RoPE + bf16 hi/lo pair packing (unchanged).
// ---------------------------------------------------------------------------
#define QK_ITEMS (BB*TT*HH*32)
#define V_ITEMS  (BB*(TT/2)*HH*64)
#define ROPE_TOTAL (2*QK_ITEMS + V_ITEMS)

__device__ __forceinline__ float rope_dim(const float* p, int d, int t) {
    const float L = 13.287712379549449f / 32.0f;  // log2(10000)/32
    int j = d & 31;
    float inv = exp2f(-(float)j * L);
    float ang = (float)t * inv;
    float c, s;
    sincosf(ang, &s, &c);
    return (d < 32) ? (p[d] * c - p[d + 32] * s)
                    : (p[d] * c + p[d - 32] * s);
}

__global__ __launch_bounds__(256)
void rope_pack_kernel()
{
    int idx = blockIdx.x * blockDim.x + threadIdx.x;
    if (idx >= ROPE_TOTAL) return;

    if (idx < 2 * QK_ITEMS) {
        int seg = idx / QK_ITEMS;        // 0: q, 1: k
        int i = idx - seg * QK_ITEMS;
        int dp = i & 31;
        int h = (i >> 5) & 15;
        int t = (i >> 9) & 2047;
        int b = i >> 20;
        size_t base = (((size_t)(b*TT + t))*HH + h) * DD;
        const float* p = (seg == 0 ? g_q : g_k) + base;
        int d0 = 2 * dp;
        float o0 = rope_dim(p, d0, t);
        float o1 = rope_dim(p, d0 + 1, t);
        float h0 = bf16f(o0), h1 = bf16f(o1);
        size_t oi = (((size_t)(b*TT + t))*HH + h) * 32 + dp;
        if (seg == 0) {
            g_qhi[oi] = pack2(h0, h1);
            g_qlo[oi] = pack2(o0 - h0, o1 - h1);
        } else {
            g_khi[oi] = pack2(h0, h1);
            g_klo[oi] = pack2(o0 - h0, o1 - h1);
        }
    } else {
        int i = idx - 2 * QK_ITEMS;
        int d = i & 63;
        int h = (i >> 6) & 15;
        int t2 = (i >> 10) & 1023;
        int b = i >> 20;
        float v0 = g_v[(((size_t)(b*TT + 2*t2    ))*HH + h) * DD + d];
        float v1 = g_v[(((size_t)(b*TT + 2*t2 + 1))*HH + h) * DD + d];
        float h0 = bf16f(v0), h1 = bf16f(v1);
        size_t oi = (((size_t)(b*(TT/2) + t2))*HH + h) * 64 + d;
        g_vhi[oi] = pack2(h0, h1);
        g_vlo[oi] = pack2(v0 - h0, v1 - h1);
    }
}

// ===========================================================================
// Tensor-core causal flash attention, bf16 hi/lo compensated.
// R15: term-major MMA scheduling — consecutive MMAs into the same
// accumulator are spaced 4 (S) / 8 (PV) apart so HMMA latency is hidden.
// Per-accumulator term order (hi*hi, hi*lo, lo*hi) preserved: bit-identical.
// ===========================================================================
#define KST 36
#define VST 72
#define ATT_STAGE_W 4608
#define ATT_SMEM_BYTES (2 * ATT_STAGE_W * 4)   // 36864

__global__ __launch_bounds__(256, 2)
void attn_kernel()
{
    extern __shared__ uint32_t smw[];
    const uint32_t smb = smem_u32(smw);

    const int tid = threadIdx.x;
    const int lane = tid & 31, wid = tid >> 5;
    const int grp = lane >> 2, tig = lane & 3;
    const int qtile = gridDim.x - 1 - blockIdx.x;
    const int bh = blockIdx.y;
    const int b = bh >> 4, h = bh & 15;
    const int q0 = qtile * 128;
    const int wr0 = wid * 16;

#define ISSUE_TILE(kt_, buf_)                                               \
    do {                                                                    \
        int k0_ = (kt_) * 32;                                               \
        uint32_t st_ = smb + (buf_) * (ATT_STAGE_W * 4);                    \
        {   /* Khi */                                                       \
            int r_ = tid >> 3, ch_ = tid & 7;                               \
            const uint32_t* s_ = g_khi + (((size_t)(b*TT + k0_ + r_))*HH + h)*32 + ch_*4; \
            asm volatile("cp.async.cg.shared.global [%0], [%1], 16;"        \
                :: "r"(st_ + r_*144 + ch_*16), "l"(s_) : "memory");         \
        }                                                                   \
        {   /* Klo */                                                       \
            int r_ = tid >> 3, ch_ = tid & 7;                               \
            const uint32_t* s_ = g_klo + (((size_t)(b*TT + k0_ + r_))*HH + h)*32 + ch_*4; \
            asm volatile("cp.async.cg.shared.global [%0], [%1], 16;"        \
                :: "r"(st_ + 4608 + r_*144 + ch_*16), "l"(s_) : "memory");  \
        }                                                                   \
        {   /* Vhi */                                                       \
            int r_ = tid >> 4, ch_ = tid & 15;                              \
            const uint32_t* s_ = g_vhi + (((size_t)(b*(TT/2) + k0_/2 + r_))*HH + h)*64 + ch_*4; \
            asm volatile("cp.async.cg.shared.global [%0], [%1], 16;"        \
                :: "r"(st_ + 9216 + r_*288 + ch_*16), "l"(s_) : "memory");  \
        }                                                                   \
        {   /* Vlo */                                                       \
            int r_ = tid >> 4, ch_ = tid & 15;                              \
            const uint32_t* s_ = g_vlo + (((size_t)(b*(TT/2) + k0_/2 + r_))*HH + h)*64 + ch_*4; \
            asm volatile("cp.async.cg.shared.global [%0], [%1], 16;"        \
                :: "r"(st_ + 13824 + r_*288 + ch_*16), "l"(s_) : "memory"); \
        }                                                                   \
    } while (0)

    ISSUE_TILE(0, 0);
    asm volatile("cp.async.commit_group;" ::: "memory");

    uint32_t qhi2[4][4], qlo2[4][4];
    {
        size_t r0i = (((size_t)(b*TT + q0 + wr0 + grp))*HH + h) * 32;
        size_t r8i = r0i + (size_t)8 * HH * 32;
#pragma unroll
        for (int ksb = 0; ksb < 4; ksb++) {
            int dp = 8*ksb + tig;
            qhi2[ksb][0] = g_qhi[r0i + dp];
            qhi2[ksb][1] = g_qhi[r8i + dp];
            qhi2[ksb][2] = g_qhi[r0i + dp + 4];
            qhi2[ksb][3] = g_qhi[r8i + dp + 4];
            qlo2[ksb][0] = g_qlo[r0i + dp];
            qlo2[ksb][1] = g_qlo[r8i + dp];
            qlo2[ksb][2] = g_qlo[r0i + dp + 4];
            qlo2[ksb][3] = g_qlo[r8i + dp + 4];
        }
    }

    float o[8][4];
#pragma unroll
    for (int nt = 0; nt < 8; nt++)
#pragma unroll
        for (int e = 0; e < 4; e++) o[nt][e] = 0.f;
    float mr0 = -1e30f, mr1 = -1e30f, lr0v = 0.f, lr1v = 0.f;

    const int row0 = q0 + wr0 + grp;
    const int row1 = row0 + 8;
    const int ntiles = 4*qtile + 4;

    for (int kt = 0; kt < ntiles; kt++) {
        int buf = kt & 1;
        int k0 = kt * 32;

        if (kt + 1 < ntiles) ISSUE_TILE(kt + 1, buf ^ 1);
        asm volatile("cp.async.commit_group;" ::: "memory");
        asm volatile("cp.async.wait_group 1;" ::: "memory");
        __syncthreads();

        if (k0 <= q0 + wr0 + 15) {
            const uint32_t* Khi_s = smw + buf * ATT_STAGE_W;
            const uint32_t* Klo_s = Khi_s + 1152;
            const uint32_t* Vhi_s = Khi_s + 2304;
            const uint32_t* Vlo_s = Khi_s + 3456;

            // ---- S = Q K^T, term-major scheduling ----
            float c[4][4];
#pragma unroll
            for (int nt = 0; nt < 4; nt++)
#pragma unroll
                for (int e = 0; e < 4; e++) c[nt][e] = 0.f;

#pragma unroll
            for (int ksb = 0; ksb < 4; ksb++) {
                int dp = 8*ksb + tig;
                // term A: qhi * Khi  (4 independent accumulators)
#pragma unroll
                for (int nt = 0; nt < 4; nt++) {
                    int krow = (nt*8 + grp) * KST;
                    uint32_t bhi[2] = {Khi_s[krow + dp], Khi_s[krow + dp + 4]};
                    mma_bf16(c[nt], qhi2[ksb], bhi);
                }
                // term B: qhi * Klo
#pragma unroll
                for (int nt = 0; nt < 4; nt++) {
                    int krow = (nt*8 + grp) * KST;
                    uint32_t blo[2] = {Klo_s[krow + dp], Klo_s[krow + dp + 4]};
                    mma_bf16(c[nt], qhi2[ksb], blo);
                }
                // term C: qlo * Khi
#pragma unroll
                for (int nt = 0; nt < 4; nt++) {
                    int krow = (nt*8 + grp) * KST;
                    uint32_t bhi[2] = {Khi_s[krow + dp], Khi_s[krow + dp + 4]};
                    mma_bf16(c[nt], qlo2[ksb], bhi);
                }
            }

            // ---- scale + causal mask ----
#pragma unroll
            for (int nt = 0; nt < 4; nt++) {
                int col = k0 + nt*8 + tig*2;
                c[nt][0] = (col     <= row0) ? c[nt][0] * 0.125f : -1e30f;
                c[nt][1] = (col + 1 <= row0) ? c[nt][1] * 0.125f : -1e30f;
                c[nt][2] = (col     <= row1) ? c[nt][2] * 0.125f : -1e30f;
                c[nt][3] = (col + 1 <= row1) ? c[nt][3] * 0.125f : -1e30f;
            }

            // ---- online softmax ----
            float mx0 = -1e30f, mx1 = -1e30f;
#pragma unroll
            for (int nt = 0; nt < 4; nt++) {
                mx0 = fmaxf(mx0, fmaxf(c[nt][0], c[nt][1]));
                mx1 = fmaxf(mx1, fmaxf(c[nt][2], c[nt][3]));
            }
            mx0 = fmaxf(mx0, __shfl_xor_sync(0xffffffffu, mx0, 1));
            mx0 = fmaxf(mx0, __shfl_xor_sync(0xffffffffu, mx0, 2));
            mx1 = fmaxf(mx1, __shfl_xor_sync(0xffffffffu, mx1, 1));
            mx1 = fmaxf(mx1, __shfl_xor_sync(0xffffffffu, mx1, 2));

            float nm0 = fmaxf(mr0, mx0), nm1 = fmaxf(mr1, mx1);
            float corr0 = __expf(mr0 - nm0), corr1 = __expf(mr1 - nm1);
            mr0 = nm0; mr1 = nm1;

            float rs0 = 0.f, rs1 = 0.f;
#pragma unroll
            for (int nt = 0; nt < 4; nt++) {
                c[nt][0] = __expf(c[nt][0] - nm0);
                c[nt][1] = __expf(c[nt][1] - nm0);
                c[nt][2] = __expf(c[nt][2] - nm1);
                c[nt][3] = __expf(c[nt][3] - nm1);
                rs0 += c[nt][0] + c[nt][1];
                rs1 += c[nt][2] + c[nt][3];
            }
            rs0 += __shfl_xor_sync(0xffffffffu, rs0, 1);
            rs0 += __shfl_xor_sync(0xffffffffu, rs0, 2);
            rs1 += __shfl_xor_sync(0xffffffffu, rs1, 1);
            rs1 += __shfl_xor_sync(0xffffffffu, rs1, 2);
            lr0v = lr0v * corr0 + rs0;
            lr1v = lr1v * corr1 + rs1;

#pragma unroll
            for (int nt = 0; nt < 8; nt++) {
                o[nt][0] *= corr0; o[nt][1] *= corr0;
                o[nt][2] *= corr1; o[nt][3] *= corr1;
            }

            // ---- O += P V, term-major scheduling ----
#pragma unroll
            for (int ksbv = 0; ksbv < 2; ksbv++) {
                float p00 = c[2*ksbv][0],   p01 = c[2*ksbv][1];
                float p02 = c[2*ksbv][2],   p03 = c[2*ksbv][3];
                float p10 = c[2*ksbv+1][0], p11 = c[2*ksbv+1][1];
                float p12 = c[2*ksbv+1][2], p13 = c[2*ksbv+1][3];
                float h00 = bf16f(p00), h01 = bf16f(p01);
                float h02 = bf16f(p02), h03 = bf16f(p03);
                float h10 = bf16f(p10), h11 = bf16f(p11);
                float h12 = bf16f(p12), h13 = bf16f(p13);
                uint32_t pah[4] = { pack2(h00, h01), pack2(h02, h03),
                                    pack2(h10, h11), pack2(h12, h13) };
                uint32_t pal[4] = { pack2(p00-h00, p01-h01), pack2(p02-h02, p03-h03),
                                    pack2(p10-h10, p11-h11), pack2(p12-h12, p13-h13) };
                int vb = (8*ksbv + tig) * VST;
                // term A: pah * Vhi  (8 independent accumulators)
#pragma unroll
                for (int nt = 0; nt < 8; nt++) {
                    int vrow0 = vb + nt*8 + grp;
                    uint32_t bhi[2] = {Vhi_s[vrow0], Vhi_s[vrow0 + 4*VST]};
                    mma_bf16(o[nt], pah, bhi);
                }
                // term B: pah * Vlo
#pragma unroll
                for (int nt = 0; nt < 8; nt++) {
                    int vrow0 = vb + nt*8 + grp;
                    uint32_t blo[2] = {Vlo_s[vrow0], Vlo_s[vrow0 + 4*VST]};
                    mma_bf16(o[nt], pah, blo);
                }
                // term C: pal * Vhi
#pragma unroll
                for (int nt = 0; nt < 8; nt++) {
                    int vrow0 = vb + nt*8 + grp;
                    uint32_t bhi[2] = {Vhi_s[vrow0], Vhi_s[vrow0 + 4*VST]};
                    mma_bf16(o[nt], pal, bhi);
                }
            }
        }
        __syncthreads();
    }
#undef ISSUE_TILE

    float i0 = 1.f / lr0v, i1 = 1.f / lr1v;
    float* y0 = g_att + ((size_t)(b*TT + q0 + wr0 + grp))*CC + h*DD;
    float* y1 = g_att + ((size_t)(b*TT + q0 + wr0 + grp + 8))*CC + h*DD;
#pragma unroll
    for (int nt = 0; nt < 8; nt++) {
        *(float2*)(y0 + nt*8 + tig*2) =
            make_float2(to_tf32(o[nt][0]*i0), to_tf32(o[nt][1]*i0));
        *(float2*)(y1 + nt*8 + tig*2) =
            make_float2(to_tf32(o[nt][2]*i1), to_tf32(o[nt][3]*i1));
    }
}

// ---------------------------------------------------------------------------
extern "C" void kernel_launch(void* const* d_in, const int* in_sizes, int n_in,
                              void* d_out, int out_size)
{
    const float* x  = (const float*)d_in[0];
    const float* Wq = (const float*)d_in[1];
    const float* bq = (const float*)d_in[2];
    const float* Wk = (const float*)d_in[3];
    const float* bk = (const float*)d_in[4];
    const float* Wv = (const float*)d_in[5];
    const float* bv = (const float*)d_in[6];
    const float* Wp = (const float*)d_in[7];
    const float* bp = (const float*)d_in[8];
    float* out = (float*)d_out;

    cudaFuncSetAttribute(attn_kernel,
                         cudaFuncAttributeMaxDynamicSharedMemorySize,
                         ATT_SMEM_BYTES);
    cudaFuncSetAttribute(mm_qkv_kernel,
                         cudaFuncAttributeMaxDynamicSharedMemorySize,
                         MM_SMEM_BYTES);
    cudaFuncSetAttribute(mm_proj_kernel,
                         cudaFuncAttributeMaxDynamicSharedMemorySize,
                         MM_SMEM_BYTES);

    // 0. Pre-round x and weights to tf32 bit patterns
    prep_round_kernel<<<(PREP_TOTAL4 + 255) / 256, 256>>>(x, Wq, Wk, Wv, Wp);

    // 1. QKV projections (tf32 mma.sync, BK=16, 4-stage cp.async)
    dim3 qkv_grid(GN/128, MM/128, 3);
    mm_qkv_kernel<<<qkv_grid, 256, MM_SMEM_BYTES>>>(bq, bk, bv);

    // 2. RoPE + bf16 hi/lo packing of Q, K, V
    rope_pack_kernel<<<(ROPE_TOTAL + 255) / 256, 256>>>();

    // 3. bf16 compensated causal flash attention (term-major mma order)
    dim3 attn_grid(TT/128, BB*HH);
    attn_kernel<<<attn_grid, 256, ATT_SMEM_BYTES>>>();

    // 4. Output projection (tf32 mma.sync, BK=16, 4-stage cp.async)
    dim3 proj_grid(GN/128, MM/128);
    mm_proj_kernel<<<proj_grid, 256, MM_SMEM_BYTES>>>(bp, out);
}

// round 16
// speedup vs baseline: 1.0874x; 1.0315x over previous
#include <cuda_runtime.h>
#include <cuda_bf16.h>
#include <math.h>
#include <stdint.h>

// Problem constants
#define BB 2
#define TT 2048
#define HH 16
#define DD 64
#define CC 1024
#define MM (BB*TT)   // 4096

// Scratch (allocation-free rule: __device__ globals)
__device__ float g_att[MM*CC];      // tf32-rounded at attention epilogue
__device__ float g_xt[MM*CC];       // tf32-rounded x
__device__ float g_wt[4*CC*CC];     // tf32-rounded Wq,Wk,Wv,Wp
// bf16 hi/lo packed planes for attention operands
__device__ uint32_t g_qhi[MM*HH*32];
__device__ uint32_t g_qlo[MM*HH*32];
__device__ uint32_t g_khi[MM*HH*32];
__device__ uint32_t g_klo[MM*HH*32];
__device__ uint32_t g_vhi[MM*HH*32];
__device__ uint32_t g_vlo[MM*HH*32];

// ---------------------------------------------------------------------------
// helpers
// ---------------------------------------------------------------------------
__device__ __forceinline__ float to_tf32(float x) {
    float r;
    asm("cvt.rna.tf32.f32 %0, %1;" : "=f"(r) : "f"(x));
    return r;
}

__device__ __forceinline__ void mma_tf32(float c[4], const uint32_t a[4],
                                         const uint32_t b[2])
{
    asm volatile(
        "mma.sync.aligned.m16n8k8.row.col.f32.tf32.tf32.f32 "
        "{%0,%1,%2,%3}, {%4,%5,%6,%7}, {%8,%9}, {%0,%1,%2,%3};"
        : "+f"(c[0]), "+f"(c[1]), "+f"(c[2]), "+f"(c[3])
        : "r"(a[0]), "r"(a[1]), "r"(a[2]), "r"(a[3]),
          "r"(b[0]), "r"(b[1]));
}

__device__ __forceinline__ void mma_bf16(float c[4], const uint32_t a[4],
                                         const uint32_t b[2])
{
    asm volatile(
        "mma.sync.aligned.m16n8k16.row.col.f32.bf16.bf16.f32 "
        "{%0,%1,%2,%3}, {%4,%5,%6,%7}, {%8,%9}, {%0,%1,%2,%3};"
        : "+f"(c[0]), "+f"(c[1]), "+f"(c[2]), "+f"(c[3])
        : "r"(a[0]), "r"(a[1]), "r"(a[2]), "r"(a[3]),
          "r"(b[0]), "r"(b[1]));
}

__device__ __forceinline__ uint32_t smem_u32(const void* p) {
    uint32_t a;
    asm("{ .reg .u64 t; cvta.to.shared.u64 t, %1; cvt.u32.u64 %0, t; }"
        : "=r"(a) : "l"(p));
    return a;
}

__device__ __forceinline__ uint32_t pack2(float e0, float e1) {
    __nv_bfloat162 t = __floats2bfloat162_rn(e0, e1);
    return *(uint32_t*)&t;
}
__device__ __forceinline__ float bf16f(float v) {
    return __bfloat162float(__float2bfloat16_rn(v));
}

// ---------------------------------------------------------------------------
// Prep: round x and the 4 weight matrices to tf32 bit patterns.
// ---------------------------------------------------------------------------
#define X4 (MM*CC/4)
#define W4 (CC*CC/4)
#define PREP_TOTAL4 (X4 + 4*W4)

__global__ __launch_bounds__(256)
void prep_round_kernel(const float* __restrict__ x,
                       const float* __restrict__ Wq, const float* __restrict__ Wk,
                       const float* __restrict__ Wv, const float* __restrict__ Wp)
{
    int i = blockIdx.x * blockDim.x + threadIdx.x;
    if (i >= PREP_TOTAL4) return;
    const float* src; float* dst; int off;
    if (i < X4) {
        src = x; dst = g_xt; off = i;
    } else {
        int j = i - X4;
        int w = j >> 18;
        off = j & (W4 - 1);
        src = (w == 0) ? Wq : (w == 1) ? Wk : (w == 2) ? Wv : Wp;
        dst = g_wt + (size_t)w * (CC*CC);
    }
    float4 v = ((const float4*)src)[off];
    v.x = to_tf32(v.x); v.y = to_tf32(v.y);
    v.z = to_tf32(v.z); v.w = to_tf32(v.w);
    ((float4*)dst)[off] = v;
}

// ===========================================================================
// tf32 mma.sync GEMM mainloop: 4-stage cp.async (confirmed R13/R15 config).
// Fills c[2][8][4]; caller applies its own epilogue.
// ===========================================================================
#define GK 1024
#define GN 1024
#define BKt 16
#define STAGES 4
#define AS_STRIDE 20
#define TILE_FLOATS (128*AS_STRIDE)
#define STAGE_BYTES (2*TILE_FLOATS*4)
#define MM_SMEM_BYTES (STAGES*STAGE_BYTES)   // 81920

__device__ __forceinline__ void mm128_loop(
    const float* __restrict__ A, const float* __restrict__ W,
    float c[2][8][4])
{
    extern __shared__ float sm[];
    uint32_t smb = smem_u32(sm);

    const int tid = threadIdx.x;
    const int wid = tid >> 5;
    const int lane = tid & 31;
    const int grp = lane >> 2;
    const int tig = lane & 3;
    const int wm = wid >> 1;
    const int wn = wid & 1;

    const int m0 = blockIdx.y * 128;
    const int n0 = blockIdx.x * 128;

    const int lr = tid >> 1;
    const int lkc = (tid & 1) * 2;

    const float* Ag = A + (size_t)(m0 + lr) * GK + lkc * 4;
    const float* Wg = W + (size_t)(n0 + lr) * GK + lkc * 4;
    const uint32_t sA = smb + (lr * AS_STRIDE + lkc * 4) * 4;
    const uint32_t sB = sA + TILE_FLOATS * 4;

#define ISSUE_MM(it_, st_)                                                  \
    do {                                                                    \
        const float* ag_ = Ag + (it_) * BKt;                                \
        const float* wg_ = Wg + (it_) * BKt;                                \
        uint32_t a_ = sA + (st_) * STAGE_BYTES;                             \
        uint32_t b_ = sB + (st_) * STAGE_BYTES;                             \
        asm volatile("cp.async.cg.shared.global [%0], [%1], 16;"            \
                     :: "r"(a_), "l"(ag_) : "memory");                      \
        asm volatile("cp.async.cg.shared.global [%0], [%1], 16;"            \
                     :: "r"(a_ + 16), "l"(ag_ + 4) : "memory");             \
        asm volatile("cp.async.cg.shared.global [%0], [%1], 16;"            \
                     :: "r"(b_), "l"(wg_) : "memory");                      \
        asm volatile("cp.async.cg.shared.global [%0], [%1], 16;"            \
                     :: "r"(b_ + 16), "l"(wg_ + 4) : "memory");             \
    } while (0)

#pragma unroll
    for (int mt = 0; mt < 2; mt++)
#pragma unroll
        for (int nt = 0; nt < 8; nt++)
#pragma unroll
            for (int i = 0; i < 4; i++) c[mt][nt][i] = 0.f;

#pragma unroll
    for (int s = 0; s < STAGES - 1; s++) {
        ISSUE_MM(s, s);
        asm volatile("cp.async.commit_group;" ::: "memory");
    }

    const int NT = GK / BKt;
    for (int it = 0; it < NT; it++) {
        asm volatile("cp.async.wait_group %0;" :: "n"(STAGES - 2) : "memory");
        __syncthreads();

        if (it + STAGES - 1 < NT)
            ISSUE_MM(it + STAGES - 1, (it + STAGES - 1) % STAGES);
        asm volatile("cp.async.commit_group;" ::: "memory");

        const float* AsS = sm + (it % STAGES) * (2 * TILE_FLOATS);
        const float* BsS = AsS + TILE_FLOATS;
#pragma unroll
        for (int ks = 0; ks < 2; ks++) {
            int kk = ks * 8;
            uint32_t afr[2][4];
#pragma unroll
            for (int mt = 0; mt < 2; mt++) {
                int rm = wm * 32 + mt * 16;
                afr[mt][0] = __float_as_uint(AsS[(rm+grp)  *AS_STRIDE + kk+tig]);
                afr[mt][1] = __float_as_uint(AsS[(rm+grp+8)*AS_STRIDE + kk+tig]);
                afr[mt][2] = __float_as_uint(AsS[(rm+grp)  *AS_STRIDE + kk+tig+4]);
                afr[mt][3] = __float_as_uint(AsS[(rm+grp+8)*AS_STRIDE + kk+tig+4]);
            }
            uint32_t bfr[8][2];
#pragma unroll
            for (int nt = 0; nt < 8; nt++) {
                int cn = wn * 64 + nt * 8;
                bfr[nt][0] = __float_as_uint(BsS[(cn+grp)*AS_STRIDE + kk+tig]);
                bfr[nt][1] = __float_as_uint(BsS[(cn+grp)*AS_STRIDE + kk+tig+4]);
            }
#pragma unroll
            for (int mt = 0; mt < 2; mt++)
#pragma unroll
                for (int nt = 0; nt < 8; nt++)
                    mma_tf32(c[mt][nt], afr[mt], bfr[nt]);
        }
    }
#undef ISSUE_MM
}

// ---------------------------------------------------------------------------
// QKV GEMM with fused bias + RoPE + bf16 hi/lo packing epilogue.
// blockIdx.z: 0=Q(rope), 1=K(rope), 2=V(key-pair pack via shuffle).
// Warp tile covers exactly one head (64 cols): rope pair (d, d+32) = frags
// (nt, nt+4) of the SAME thread; V row pair (r, r+1) = lane, lane+4.
// ---------------------------------------------------------------------------
__global__ __launch_bounds__(256, 2)
void mm_qkv_fused(const float* __restrict__ bq,
                  const float* __restrict__ bk,
                  const float* __restrict__ bv)
{
    float c[2][8][4];
    const float* W = g_wt + (size_t)blockIdx.z * (CC*CC);
    mm128_loop(g_xt, W, c);

    const int tid = threadIdx.x;
    const int wid = tid >> 5, lane = tid & 31;
    const int grp = lane >> 2, tig = lane & 3;
    const int wm = wid >> 1, wn = wid & 1;
    const int m0 = blockIdx.y * 128, n0 = blockIdx.x * 128;
    const int h = (n0 >> 6) + wn;
    const int seg = blockIdx.z;
    const float* bias = (seg == 0) ? bq : (seg == 1) ? bk : bv;

    // bias add
#pragma unroll
    for (int mt = 0; mt < 2; mt++)
#pragma unroll
        for (int nt = 0; nt < 8; nt++) {
            int col = n0 + wn*64 + nt*8 + tig*2;
            float2 bv2 = *(const float2*)(bias + col);
            c[mt][nt][0] += bv2.x; c[mt][nt][1] += bv2.y;
            c[mt][nt][2] += bv2.x; c[mt][nt][3] += bv2.y;
        }

    if (seg < 2) {
        uint32_t* ghi = (seg == 0) ? g_qhi : g_khi;
        uint32_t* glo = (seg == 0) ? g_qlo : g_klo;
        const float L = 13.287712379549449f / 32.0f;  // log2(10000)/32
#pragma unroll
        for (int mt = 0; mt < 2; mt++) {
#pragma unroll
            for (int ri = 0; ri < 2; ri++) {
                int row = m0 + wm*32 + mt*16 + ri*8 + grp;
                int t = row & (TT - 1);
                int bb2 = row >> 11;
                size_t base = (((size_t)(bb2*TT + t))*HH + h) * 32;
#pragma unroll
                for (int nt = 0; nt < 4; nt++) {
                    int j = nt*8 + tig*2;            // < 32
                    float inv0 = exp2f(-(float)j * L);
                    float inv1 = exp2f(-(float)(j + 1) * L);
                    float s0, c0, s1, c1;
                    sincosf((float)t * inv0, &s0, &c0);
                    sincosf((float)t * inv1, &s1, &c1);
                    float x1a = c[mt][nt][2*ri],   x1b = c[mt][nt][2*ri+1];
                    float x2a = c[mt][nt+4][2*ri], x2b = c[mt][nt+4][2*ri+1];
                    float rla = x1a*c0 - x2a*s0;   // dim j
                    float rlb = x1b*c1 - x2b*s1;   // dim j+1
                    float rha = x2a*c0 + x1a*s0;   // dim j+32
                    float rhb = x2b*c1 + x1b*s1;   // dim j+33
                    float ha = bf16f(rla), hb = bf16f(rlb);
                    ghi[base + nt*4 + tig] = pack2(ha, hb);
                    glo[base + nt*4 + tig] = pack2(rla - ha, rlb - hb);
                    ha = bf16f(rha); hb = bf16f(rhb);
                    ghi[base + 16 + nt*4 + tig] = pack2(ha, hb);
                    glo[base + 16 + nt*4 + tig] = pack2(rha - ha, rhb - hb);
                }
            }
        }
    } else {
        // V: pack key pairs (row r even, r+1) per dim; partner via shfl_down 4
#pragma unroll
        for (int mt = 0; mt < 2; mt++) {
#pragma unroll
            for (int ri = 0; ri < 2; ri++) {
                int row = m0 + wm*32 + mt*16 + ri*8 + grp;
                int t = row & (TT - 1);
                int bb2 = row >> 11;
                size_t base = (((size_t)(bb2*(TT/2) + (t >> 1)))*HH + h) * 64;
#pragma unroll
                for (int nt = 0; nt < 8; nt++) {
                    float va = c[mt][nt][2*ri], vb = c[mt][nt][2*ri+1];
                    float na = __shfl_down_sync(0xffffffffu, va, 4);
                    float nb = __shfl_down_sync(0xffffffffu, vb, 4);
                    if (!(grp & 1)) {
                        int d = nt*8 + tig*2;
                        float ha = bf16f(va), hn = bf16f(na);
                        g_vhi[base + d] = pack2(ha, hn);
                        g_vlo[base + d] = pack2(va - ha, na - hn);
                        float hb = bf16f(vb), hm = bf16f(nb);
                        g_vhi[base + d + 1] = pack2(hb, hm);
                        g_vlo[base + d + 1] = pack2(vb - hb, nb - hm);
                    }
                }
            }
        }
    }
}

// ---------------------------------------------------------------------------
// Output projection: mainloop + plain bias epilogue (unchanged behavior).
// ---------------------------------------------------------------------------
__global__ __launch_bounds__(256, 2)
void mm_proj_kernel(const float* __restrict__ bp, float* __restrict__ out)
{
    float c[2][8][4];
    mm128_loop(g_att, g_wt + (size_t)3 * (CC*CC), c);

    const int tid = threadIdx.x;
    const int wid = tid >> 5, lane = tid & 31;
    const int grp = lane >> 2, tig = lane & 3;
    const int wm = wid >> 1, wn = wid & 1;
    const int m0 = blockIdx.y * 128, n0 = blockIdx.x * 128;

#pragma unroll
    for (int mt = 0; mt < 2; mt++) {
        int row = m0 + wm*32 + mt*16 + grp;
#pragma unroll
        for (int nt = 0; nt < 8; nt++) {
            int col = n0 + wn*64 + nt*8 + tig*2;
            float2 bv = *(const float2*)(bp + col);
            float2 o0, o1;
            o0.x = c[mt][nt][0] + bv.x;
            o0.y = c[mt][nt][1] + bv.y;
            o1.x = c[mt][nt][2] + bv.x;
            o1.y = c[mt][nt][3] + bv.y;
            *(float2*)(out + (size_t)row * GN + col) = o0;
            *(float2*)(out + (size_t)(row + 8) * GN + col) = o1;
        }
    }
}

// ===========================================================================
// Tensor-core causal flash attention, bf16 hi/lo compensated (R15 version).
// ===========================================================================
#define KST 36
#define VST 72
#define ATT_STAGE_W 4608
#define ATT_SMEM_BYTES (2 * ATT_STAGE_W * 4)   // 36864

__global__ __launch_bounds__(256, 2)
void attn_kernel()
{
    extern __shared__ uint32_t smw[];
    const uint32_t smb = smem_u32(smw);

    const int tid = threadIdx.x;
    const int lane = tid & 31, wid = tid >> 5;
    const int grp = lane >> 2, tig = lane & 3;
    const int qtile = gridDim.x - 1 - blockIdx.x;
    const int bh = blockIdx.y;
    const int b = bh >> 4, h = bh & 15;
    const int q0 = qtile * 128;
    const int wr0 = wid * 16;

#define ISSUE_TILE(kt_, buf_)                                               \
    do {                                                                    \
        int k0_ = (kt_) * 32;                                               \
        uint32_t st_ = smb + (buf_) * (ATT_STAGE_W * 4);                    \
        {   /* Khi */                                                       \
            int r_ = tid >> 3, ch_ = tid & 7;                               \
            const uint32_t* s_ = g_khi + (((size_t)(b*TT + k0_ + r_))*HH + h)*32 + ch_*4; \
            asm volatile("cp.async.cg.shared.global [%0], [%1], 16;"        \
                :: "r"(st_ + r_*144 + ch_*16), "l"(s_) : "memory");         \
        }                                                                   \
        {   /* Klo */                                                       \
            int r_ = tid >> 3, ch_ = tid & 7;                               \
            const uint32_t* s_ = g_klo + (((size_t)(b*TT + k0_ + r_))*HH + h)*32 + ch_*4; \
            asm volatile("cp.async.cg.shared.global [%0], [%1], 16;"        \
                :: "r"(st_ + 4608 + r_*144 + ch_*16), "l"(s_) : "memory");  \
        }                                                                   \
        {   /* Vhi */                                                       \
            int r_ = tid >> 4, ch_ = tid & 15;                              \
            const uint32_t* s_ = g_vhi + (((size_t)(b*(TT/2) + k0_/2 + r_))*HH + h)*64 + ch_*4; \
            asm volatile("cp.async.cg.shared.global [%0], [%1], 16;"        \
                :: "r"(st_ + 9216 + r_*288 + ch_*16), "l"(s_) : "memory");  \
        }                                                                   \
        {   /* Vlo */                                                       \
            int r_ = tid >> 4, ch_ = tid & 15;                              \
            const uint32_t* s_ = g_vlo + (((size_t)(b*(TT/2) + k0_/2 + r_))*HH + h)*64 + ch_*4; \
            asm volatile("cp.async.cg.shared.global [%0], [%1], 16;"        \
                :: "r"(st_ + 13824 + r_*288 + ch_*16), "l"(s_) : "memory"); \
        }                                                                   \
    } while (0)

    ISSUE_TILE(0, 0);
    asm volatile("cp.async.commit_group;" ::: "memory");

    uint32_t qhi2[4][4], qlo2[4][4];
    {
        size_t r0i = (((size_t)(b*TT + q0 + wr0 + grp))*HH + h) * 32;
        size_t r8i = r0i + (size_t)8 * HH * 32;
#pragma unroll
        for (int ksb = 0; ksb < 4; ksb++) {
            int dp = 8*ksb + tig;
            qhi2[ksb][0] = g_qhi[r0i + dp];
            qhi2[ksb][1] = g_qhi[r8i + dp];
            qhi2[ksb][2] = g_qhi[r0i + dp + 4];
            qhi2[ksb][3] = g_qhi[r8i + dp + 4];
            qlo2[ksb][0] = g_qlo[r0i + dp];
            qlo2[ksb][1] = g_qlo[r8i + dp];
            qlo2[ksb][2] = g_qlo[r0i + dp + 4];
            qlo2[ksb][3] = g_qlo[r8i + dp + 4];
        }
    }

    float o[8][4];
#pragma unroll
    for (int nt = 0; nt < 8; nt++)
#pragma unroll
        for (int e = 0; e < 4; e++) o[nt][e] = 0.f;
    float mr0 = -1e30f, mr1 = -1e30f, lr0v = 0.f, lr1v = 0.f;

    const int row0 = q0 + wr0 + grp;
    const int row1 = row0 + 8;
    const int ntiles = 4*qtile + 4;

    for (int kt = 0; kt < ntiles; kt++) {
        int buf = kt & 1;
        int k0 = kt * 32;

        if (kt + 1 < ntiles) ISSUE_TILE(kt + 1, buf ^ 1);
        asm volatile("cp.async.commit_group;" ::: "memory");
        asm volatile("cp.async.wait_group 1;" ::: "memory");
        __syncthreads();

        if (k0 <= q0 + wr0 + 15) {
            const uint32_t* Khi_s = smw + buf * ATT_STAGE_W;
            const uint32_t* Klo_s = Khi_s + 1152;
            const uint32_t* Vhi_s = Khi_s + 2304;
            const uint32_t* Vlo_s = Khi_s + 3456;

            float c[4][4];
#pragma unroll
            for (int nt = 0; nt < 4; nt++)
#pragma unroll
                for (int e = 0; e < 4; e++) c[nt][e] = 0.f;

#pragma unroll
            for (int ksb = 0; ksb < 4; ksb++) {
                int dp = 8*ksb + tig;
#pragma unroll
                for (int nt = 0; nt < 4; nt++) {
                    int krow = (nt*8 + grp) * KST;
                    uint32_t bhi[2] = {Khi_s[krow + dp], Khi_s[krow + dp + 4]};
                    mma_bf16(c[nt], qhi2[ksb], bhi);
                }
#pragma unroll
                for (int nt = 0; nt < 4; nt++) {
                    int krow = (nt*8 + grp) * KST;
                    uint32_t blo[2] = {Klo_s[krow + dp], Klo_s[krow + dp + 4]};
                    mma_bf16(c[nt], qhi2[ksb], blo);
                }
#pragma unroll
                for (int nt = 0; nt < 4; nt++) {
                    int krow = (nt*8 + grp) * KST;
                    uint32_t bhi[2] = {Khi_s[krow + dp], Khi_s[krow + dp + 4]};
                    mma_bf16(c[nt], qlo2[ksb], bhi);
                }
            }

#pragma unroll
            for (int nt = 0; nt < 4; nt++) {
                int col = k0 + nt*8 + tig*2;
                c[nt][0] = (col     <= row0) ? c[nt][0] * 0.125f : -1e30f;
                c[nt][1] = (col + 1 <= row0) ? c[nt][1] * 0.125f : -1e30f;
                c[nt][2] = (col     <= row1) ? c[nt][2] * 0.125f : -1e30f;
                c[nt][3] = (col + 1 <= row1) ? c[nt][3] * 0.125f : -1e30f;
            }

            float mx0 = -1e30f, mx1 = -1e30f;
#pragma unroll
            for (int nt = 0; nt < 4; nt++) {
                mx0 = fmaxf(mx0, fmaxf(c[nt][0], c[nt][1]));
                mx1 = fmaxf(mx1, fmaxf(c[nt][2], c[nt][3]));
            }
            mx0 = fmaxf(mx0, __shfl_xor_sync(0xffffffffu, mx0, 1));
            mx0 = fmaxf(mx0, __shfl_xor_sync(0xffffffffu, mx0, 2));
            mx1 = fmaxf(mx1, __shfl_xor_sync(0xffffffffu, mx1, 1));
            mx1 = fmaxf(mx1, __shfl_xor_sync(0xffffffffu, mx1, 2));

            float nm0 = fmaxf(mr0, mx0), nm1 = fmaxf(mr1, mx1);
            float corr0 = __expf(mr0 - nm0), corr1 = __expf(mr1 - nm1);
            mr0 = nm0; mr1 = nm1;

            float rs0 = 0.f, rs1 = 0.f;
#pragma unroll
            for (int nt = 0; nt < 4; nt++) {
                c[nt][0] = __expf(c[nt][0] - nm0);
                c[nt][1] = __expf(c[nt][1] - nm0);
                c[nt][2] = __expf(c[nt][2] - nm1);
                c[nt][3] = __expf(c[nt][3] - nm1);
                rs0 += c[nt][0] + c[nt][1];
                rs1 += c[nt][2] + c[nt][3];
            }
            rs0 += __shfl_xor_sync(0xffffffffu, rs0, 1);
            rs0 += __shfl_xor_sync(0xffffffffu, rs0, 2);
            rs1 += __shfl_xor_sync(0xffffffffu, rs1, 1);
            rs1 += __shfl_xor_sync(0xffffffffu, rs1, 2);
            lr0v = lr0v * corr0 + rs0;
            lr1v = lr1v * corr1 + rs1;

#pragma unroll
            for (int nt = 0; nt < 8; nt++) {
                o[nt][0] *= corr0; o[nt][1] *= corr0;
                o[nt][2] *= corr1; o[nt][3] *= corr1;
            }

#pragma unroll
            for (int ksbv = 0; ksbv < 2; ksbv++) {
                float p00 = c[2*ksbv][0],   p01 = c[2*ksbv][1];
                float p02 = c[2*ksbv][2],   p03 = c[2*ksbv][3];
                float p10 = c[2*ksbv+1][0], p11 = c[2*ksbv+1][1];
                float p12 = c[2*ksbv+1][2], p13 = c[2*ksbv+1][3];
                float h00 = bf16f(p00), h01 = bf16f(p01);
                float h02 = bf16f(p02), h03 = bf16f(p03);
                float h10 = bf16f(p10), h11 = bf16f(p11);
                float h12 = bf16f(p12), h13 = bf16f(p13);
                uint32_t pah[4] = { pack2(h00, h01), pack2(h02, h03),
                                    pack2(h10, h11), pack2(h12, h13) };
                uint32_t pal[4] = { pack2(p00-h00, p01-h01), pack2(p02-h02, p03-h03),
                                    pack2(p10-h10, p11-h11), pack2(p12-h12, p13-h13) };
                int vb = (8*ksbv + tig) * VST;
#pragma unroll
                for (int nt = 0; nt < 8; nt++) {
                    int vrow0 = vb + nt*8 + grp;
                    uint32_t bhi[2] = {Vhi_s[vrow0], Vhi_s[vrow0 + 4*VST]};
                    mma_bf16(o[nt], pah, bhi);
                }
#pragma unroll
                for (int nt = 0; nt < 8; nt++) {
                    int vrow0 = vb + nt*8 + grp;
                    uint32_t blo[2] = {Vlo_s[vrow0], Vlo_s[vrow0 + 4*VST]};
                    mma_bf16(o[nt], pah, blo);
                }
#pragma unroll
                for (int nt = 0; nt < 8; nt++) {
                    int vrow0 = vb + nt*8 + grp;
                    uint32_t bhi[2] = {Vhi_s[vrow0], Vhi_s[vrow0 + 4*VST]};
                    mma_bf16(o[nt], pal, bhi);
                }
            }
        }
        __syncthreads();
    }
#undef ISSUE_TILE

    float i0 = 1.f / lr0v, i1 = 1.f / lr1v;
    float* y0 = g_att + ((size_t)(b*TT + q0 + wr0 + grp))*CC + h*DD;
    float* y1 = g_att + ((size_t)(b*TT + q0 + wr0 + grp + 8))*CC + h*DD;
#pragma unroll
    for (int nt = 0; nt < 8; nt++) {
        *(float2*)(y0 + nt*8 + tig*2) =
            make_float2(to_tf32(o[nt][0]*i0), to_tf32(o[nt][1]*i0));
        *(float2*)(y1 + nt*8 + tig*2) =
            make_float2(to_tf32(o[nt][2]*i1), to_tf32(o[nt][3]*i1));
    }
}

// ---------------------------------------------------------------------------
extern "C" void kernel_launch(void* const* d_in, const int* in_sizes, int n_in,
                              void* d_out, int out_size)
{
    const float* x  = (const float*)d_in[0];
    const float* Wq = (const float*)d_in[1];
    const float* bq = (const float*)d_in[2];
    const float* Wk = (const float*)d_in[3];
    const float* bk = (const float*)d_in[4];
    const float* Wv = (const float*)d_in[5];
    const float* bv = (const float*)d_in[6];
    const float* Wp = (const float*)d_in[7];
    const float* bp = (const float*)d_in[8];
    float* out = (float*)d_out;

    cudaFuncSetAttribute(attn_kernel,
                         cudaFuncAttributeMaxDynamicSharedMemorySize,
                         ATT_SMEM_BYTES);
    cudaFuncSetAttribute(mm_qkv_fused,
                         cudaFuncAttributeMaxDynamicSharedMemorySize,
                         MM_SMEM_BYTES);
    cudaFuncSetAttribute(mm_proj_kernel,
                         cudaFuncAttributeMaxDynamicSharedMemorySize,
                         MM_SMEM_BYTES);

    // 0. Pre-round x and weights to tf32 bit patterns
    prep_round_kernel<<<(PREP_TOTAL4 + 255) / 256, 256>>>(x, Wq, Wk, Wv, Wp);

    // 1. QKV projections with fused bias + RoPE + bf16 hi/lo pack epilogue
    dim3 qkv_grid(GN/128, MM/128, 3);
    mm_qkv_fused<<<qkv_grid, 256, MM_SMEM_BYTES>>>(bq, bk, bv);

    // 2. bf16 compensated causal flash attention
    dim3 attn_grid(TT/128, BB*HH);
    attn_kernel<<<attn_grid, 256, ATT_SMEM_BYTES>>>();

    // 3. Output projection
    dim3 proj_grid(GN/128, MM/128);
    mm_proj_kernel<<<proj_grid, 256, MM_SMEM_BYTES>>>(bp, out);
}